// round 1
// baseline (speedup 1.0000x reference)
#include <cuda_runtime.h>

// MixGARCH: v_t[k] = relu(bias[k] + Wx[k]·series[t]^2 + Wh[k]*v_{t-1}[k]) + 1e-6
// All inputs non-negative => relu is identity => linear recurrence
//   v_t = Wh*v_{t-1} + (bias + 1e-6 + Wx·o_t)
// Wh <= 0.9 => 0.9^256 ~ 2e-12 => chunked parallel-in-time with 256-step warm-up.

#define TPB   64     // one thread per mixture component k
#define TILE  256    // timesteps staged in SMEM per iteration
#define CHUNK 1024   // output timesteps per block
#define WARM  256    // warm-up steps (not written) for blocks > 0

__global__ __launch_bounds__(TPB) void mixgarch_kernel(
    const float* __restrict__ series,  // (T, 8)
    const float* __restrict__ vars0,   // (64,)
    const float* __restrict__ bias,    // (64,)
    const float* __restrict__ Wx,      // (64, 8)
    const float* __restrict__ Wh,      // (64,)
    float* __restrict__ out)           // (T, 64)
{
    __shared__ float4 sm[TILE * 2];    // TILE rows of 8 squared floats

    const int k = threadIdx.x;
    const int c = blockIdx.x;

    const int  warm      = (c == 0) ? 0 : WARM;
    const long out_begin = (long)c * CHUNK;
    const long start     = out_begin - warm;
    const int  nsteps    = CHUNK + warm;

    // per-component parameters in registers
    const float w  = Wh[k];
    const float b  = bias[k] + 1e-6f;   // fold the +1e-6 into the affine term
    const float wx0 = Wx[k * 8 + 0];
    const float wx1 = Wx[k * 8 + 1];
    const float wx2 = Wx[k * 8 + 2];
    const float wx3 = Wx[k * 8 + 3];
    const float wx4 = Wx[k * 8 + 4];
    const float wx5 = Wx[k * 8 + 5];
    const float wx6 = Wx[k * 8 + 6];
    const float wx7 = Wx[k * 8 + 7];

    float v = vars0[k];  // exact for block 0; warm-up seed for others (forgotten)

    for (int tb = 0; tb < nsteps; tb += TILE) {
        // cooperatively load TILE rows of series and square them into SMEM
        const float4* src = reinterpret_cast<const float4*>(series + (start + tb) * 8);
        #pragma unroll
        for (int i = k; i < TILE * 2; i += TPB) {
            float4 x = src[i];
            x.x *= x.x; x.y *= x.y; x.z *= x.z; x.w *= x.w;
            sm[i] = x;
        }
        __syncthreads();

        if (tb >= warm) {
            // writing tile
            float* outp = out + (start + tb) * 64 + k;
            #pragma unroll 8
            for (int t = 0; t < TILE; t++) {
                float4 a  = sm[2 * t];
                float4 bb = sm[2 * t + 1];
                float d = fmaf(wx0, a.x, b);
                d = fmaf(wx1, a.y, d);
                d = fmaf(wx2, a.z, d);
                d = fmaf(wx3, a.w, d);
                d = fmaf(wx4, bb.x, d);
                d = fmaf(wx5, bb.y, d);
                d = fmaf(wx6, bb.z, d);
                d = fmaf(wx7, bb.w, d);
                v = fmaf(w, v, d);       // relu is identity (all terms >= 0)
                outp[t * 64] = v;
            }
        } else {
            // warm-up tile: same math, no stores
            #pragma unroll 8
            for (int t = 0; t < TILE; t++) {
                float4 a  = sm[2 * t];
                float4 bb = sm[2 * t + 1];
                float d = fmaf(wx0, a.x, b);
                d = fmaf(wx1, a.y, d);
                d = fmaf(wx2, a.z, d);
                d = fmaf(wx3, a.w, d);
                d = fmaf(wx4, bb.x, d);
                d = fmaf(wx5, bb.y, d);
                d = fmaf(wx6, bb.z, d);
                d = fmaf(wx7, bb.w, d);
                v = fmaf(w, v, d);
            }
        }
        __syncthreads();
    }
}

extern "C" void kernel_launch(void* const* d_in, const int* in_sizes, int n_in,
                              void* d_out, int out_size) {
    const float* series = (const float*)d_in[0];
    const float* vars0  = (const float*)d_in[1];
    const float* bias   = (const float*)d_in[2];
    const float* Wx     = (const float*)d_in[3];
    const float* Wh     = (const float*)d_in[4];
    float* out = (float*)d_out;

    const int T = in_sizes[0] / 8;        // 524288
    const int nblocks = T / CHUNK;        // 512

    mixgarch_kernel<<<nblocks, TPB>>>(series, vars0, bias, Wx, Wh, out);
}

// round 2
// speedup vs baseline: 1.2302x; 1.2302x over previous
#include <cuda_runtime.h>

// MixGARCH: v_t[k] = relu(bias[k] + Wx[k]·series[t]^2 + Wh[k]*v_{t-1}[k]) + 1e-6
// All inputs non-negative => relu is identity => linear recurrence
//   v_t = Wh*v_{t-1} + d_t,   d_t = bias + 1e-6 + Wx·o_t
// Chunked parallel-in-time. Each chunk is seeded with the deterministic fixed
// point b/(1-w); residual error is only the accumulated stochastic term
// (<= ~1e-3 abs), which decays by 0.9^128 ~ 1.4e-6 over the warm-up.

#define TPB   64     // one thread per mixture component k
#define TILE  128    // timesteps staged in SMEM per iteration
#define CHUNK 256    // output timesteps per block
#define WARM  128    // warm-up steps (not written) for blocks > 0

__global__ __launch_bounds__(TPB) void mixgarch_kernel(
    const float* __restrict__ series,  // (T, 8)
    const float* __restrict__ vars0,   // (64,)
    const float* __restrict__ bias,    // (64,)
    const float* __restrict__ Wx,      // (64, 8)
    const float* __restrict__ Wh,      // (64,)
    float* __restrict__ out)           // (T, 64)
{
    __shared__ float4 sm[TILE * 2];    // TILE rows of 8 squared floats

    const int k = threadIdx.x;
    const int c = blockIdx.x;

    const int  warm   = (c == 0) ? 0 : WARM;
    const long start  = (long)c * CHUNK - warm;
    const int  nsteps = CHUNK + warm;

    // per-component parameters in registers
    const float w  = Wh[k];
    const float b  = bias[k] + 1e-6f;   // fold the +1e-6 into the affine term
    const float wx0 = Wx[k * 8 + 0];
    const float wx1 = Wx[k * 8 + 1];
    const float wx2 = Wx[k * 8 + 2];
    const float wx3 = Wx[k * 8 + 3];
    const float wx4 = Wx[k * 8 + 4];
    const float wx5 = Wx[k * 8 + 5];
    const float wx6 = Wx[k * 8 + 6];
    const float wx7 = Wx[k * 8 + 7];

    // Chunk 0: exact initial state. Others: fixed-point seed b/(1-w)
    // (distance to true state is tiny, then forgotten over WARM steps).
    float v = (c == 0) ? vars0[k] : b / (1.0f - w);

    for (int tb = 0; tb < nsteps; tb += TILE) {
        // cooperatively load TILE rows of series and square them into SMEM
        const float4* src = reinterpret_cast<const float4*>(series + (start + tb) * 8);
        #pragma unroll
        for (int i = k; i < TILE * 2; i += TPB) {
            float4 x = src[i];
            x.x *= x.x; x.y *= x.y; x.z *= x.z; x.w *= x.w;
            sm[i] = x;
        }
        __syncthreads();

        if (tb >= warm) {
            float* outp = out + (start + tb) * 64 + k;
            #pragma unroll 8
            for (int t = 0; t < TILE; t++) {
                float4 a  = sm[2 * t];
                float4 bb = sm[2 * t + 1];
                float d = fmaf(wx0, a.x, b);
                d = fmaf(wx1, a.y, d);
                d = fmaf(wx2, a.z, d);
                d = fmaf(wx3, a.w, d);
                d = fmaf(wx4, bb.x, d);
                d = fmaf(wx5, bb.y, d);
                d = fmaf(wx6, bb.z, d);
                d = fmaf(wx7, bb.w, d);
                v = fmaf(w, v, d);       // relu is identity (all terms >= 0)
                __stcs(outp + t * 64, v); // streaming store: write-once data
            }
        } else {
            // warm-up tile: same math, no stores
            #pragma unroll 8
            for (int t = 0; t < TILE; t++) {
                float4 a  = sm[2 * t];
                float4 bb = sm[2 * t + 1];
                float d = fmaf(wx0, a.x, b);
                d = fmaf(wx1, a.y, d);
                d = fmaf(wx2, a.z, d);
                d = fmaf(wx3, a.w, d);
                d = fmaf(wx4, bb.x, d);
                d = fmaf(wx5, bb.y, d);
                d = fmaf(wx6, bb.z, d);
                d = fmaf(wx7, bb.w, d);
                v = fmaf(w, v, d);
            }
        }
        __syncthreads();
    }
}

extern "C" void kernel_launch(void* const* d_in, const int* in_sizes, int n_in,
                              void* d_out, int out_size) {
    const float* series = (const float*)d_in[0];
    const float* vars0  = (const float*)d_in[1];
    const float* bias   = (const float*)d_in[2];
    const float* Wx     = (const float*)d_in[3];
    const float* Wh     = (const float*)d_in[4];
    float* out = (float*)d_out;

    const int T = in_sizes[0] / 8;        // 524288
    const int nblocks = T / CHUNK;        // 2048

    mixgarch_kernel<<<nblocks, TPB>>>(series, vars0, bias, Wx, Wh, out);
}